// round 1
// baseline (speedup 1.0000x reference)
#include <cuda_runtime.h>
#include <cstdint>

// Problem constants
#define Nn      100000
#define M1ROWS  600000          // N + N*S1 layer-1 rows
typedef unsigned long long ull;

// ---- device scratch (allocation-free requirement: static device globals) ----
__device__ float g_W1c[256 * 256];          // combined layer-1 weights, K-major, (t,z) interleaved cols
__device__ float g_W2c[256 * 128];          // combined layer-2 weights
__device__ float g_outs[(size_t)M1ROWS * 128];  // out_s = [h0p ; h1p]  (307 MB)

// ---- packed f32x2 helpers (Blackwell FFMA2) ----
__device__ __forceinline__ ull pack2(float a) {
    ull r; asm("mov.b64 %0, {%1, %1};" : "=l"(r) : "f"(a)); return r;
}
__device__ __forceinline__ void fma2(ull& acc, ull a, ull b) {
    asm("fma.rn.f32x2 %0, %1, %2, %0;" : "+l"(acc) : "l"(a), "l"(b));
}
__device__ __forceinline__ float lo32(ull v) { return __uint_as_float((unsigned)v); }
__device__ __forceinline__ float hi32(ull v) { return __uint_as_float((unsigned)(v >> 32)); }

__device__ __forceinline__ float sigmoid_spike(float t, float z) {
    float sig = 1.0f / (1.0f + __expf(-z));
    return (t >= 1.0f) ? sig : 0.0f;
}

// ============================================================================
// Weight prep: interleave (t,z) per hidden unit, K-major.
//  W1c[k][n], n = 2h (+1 for z):  k<128 -> Wlt1/Wl1[h][k],  k>=128 -> Wrt1/Wr1[h][k-128]
//  W2c[k][n], n = 2h (+1 for z):  k<128 -> Wlt2/Wl2[h][k],  k>=128 -> Wrt2/Wr2[h][k-128]
// ============================================================================
__global__ void prep_kernel(const float* __restrict__ Wl1, const float* __restrict__ Wr1,
                            const float* __restrict__ Wlt1, const float* __restrict__ Wrt1,
                            const float* __restrict__ Wl2, const float* __restrict__ Wr2,
                            const float* __restrict__ Wlt2, const float* __restrict__ Wrt2)
{
    int idx = blockIdx.x * blockDim.x + threadIdx.x;
    if (idx < 256 * 256) {
        int k = idx >> 8, n = idx & 255, h = n >> 1;
        bool zsel = n & 1;
        float v;
        if (k < 128) v = zsel ? Wl1[h * 128 + k] : Wlt1[h * 128 + k];
        else         v = zsel ? Wr1[h * 128 + (k - 128)] : Wrt1[h * 128 + (k - 128)];
        g_W1c[idx] = v;
    }
    if (idx < 256 * 128) {
        int k = idx >> 7, n = idx & 127, h = n >> 1;
        bool zsel = n & 1;
        float v;
        if (k < 128) v = zsel ? Wl2[h * 128 + k] : Wlt2[h * 128 + k];
        else         v = zsel ? Wr2[h * 128 + (k - 128)] : Wrt2[h * 128 + (k - 128)];
        g_W2c[idx] = v;
    }
}

// ============================================================================
// Layer 1: rows r in [0, 600000).
//   r <  N: A = [h0[r] | mean(h1[5r..5r+5))]
//   r >= N: A = [h1[r-N] | mean(h2[2(r-N)..+2))]
//   out = A @ W1c ; out_s[r][h] = sigmoid(z_h) * (t_h >= 1)
// Tile: 64 rows x 256 cols, 256 threads, per-thread 8x8 (4 f32x2 col pairs).
// ============================================================================
extern "C" __global__ void __launch_bounds__(256, 2)
layer1_kernel(const float* __restrict__ h0, const float* __restrict__ h1,
              const float* __restrict__ h2)
{
    extern __shared__ float sm[];
    float* As = sm;                 // [64][256]
    float* Bs = sm + 64 * 256;      // [16][256]

    const int tid = threadIdx.x;
    const int row0 = blockIdx.x * 64;

    // ---- build A tile (fused neighbor averaging) ----
    {
        const int m  = tid >> 2;            // row within tile
        const int q4 = (tid & 3) * 8;       // float4 offset (32 floats per quarter)
        const int r  = row0 + m;
        float* Arow = As + m * 256;
        if (r < Nn) {
            const float4* xs = (const float4*)(h0 + (size_t)r * 128);
            const float4* n0 = (const float4*)(h1 + (size_t)r * 5 * 128);
            #pragma unroll
            for (int i = 0; i < 8; i++) {
                int k4 = q4 + i;
                *(float4*)(Arow + k4 * 4) = xs[k4];
                float4 a = n0[k4], b = n0[32 + k4], c = n0[64 + k4],
                       d = n0[96 + k4], e = n0[128 + k4];
                float4 s;
                s.x = (a.x + b.x + c.x + d.x + e.x) * 0.2f;
                s.y = (a.y + b.y + c.y + d.y + e.y) * 0.2f;
                s.z = (a.z + b.z + c.z + d.z + e.z) * 0.2f;
                s.w = (a.w + b.w + c.w + d.w + e.w) * 0.2f;
                *(float4*)(Arow + 128 + k4 * 4) = s;
            }
        } else {
            const int rr = r - Nn;
            const float4* xs = (const float4*)(h1 + (size_t)rr * 128);
            const float4* n0 = (const float4*)(h2 + (size_t)rr * 2 * 128);
            #pragma unroll
            for (int i = 0; i < 8; i++) {
                int k4 = q4 + i;
                *(float4*)(Arow + k4 * 4) = xs[k4];
                float4 a = n0[k4], b = n0[32 + k4];
                float4 s;
                s.x = (a.x + b.x) * 0.5f;
                s.y = (a.y + b.y) * 0.5f;
                s.z = (a.z + b.z) * 0.5f;
                s.w = (a.w + b.w) * 0.5f;
                *(float4*)(Arow + 128 + k4 * 4) = s;
            }
        }
    }

    ull acc[8][4];
    #pragma unroll
    for (int i = 0; i < 8; i++)
        #pragma unroll
        for (int j = 0; j < 4; j++) acc[i][j] = 0ULL;

    const int ty = tid >> 5;   // warp id -> row group (8 rows)
    const int tx = tid & 31;   // col group (8 cols = 4 pairs)

    // prefetch B tile 0 (16x256 floats = 1024 float4, 4 per thread)
    float4 pre[4];
    {
        const float4* W4 = (const float4*)g_W1c;
        #pragma unroll
        for (int j = 0; j < 4; j++) pre[j] = W4[tid + j * 256];
    }
    __syncthreads();   // As ready

    for (int kt = 0; kt < 16; kt++) {
        #pragma unroll
        for (int j = 0; j < 4; j++) {
            int lin = tid + j * 256;
            *(float4*)(Bs + lin * 4) = pre[j];
        }
        __syncthreads();
        if (kt + 1 < 16) {
            const float4* W4 = (const float4*)(g_W1c + (kt + 1) * 16 * 256);
            #pragma unroll
            for (int j = 0; j < 4; j++) pre[j] = W4[tid + j * 256];
        }
        const float* Ar = As + ty * 8 * 256 + kt * 16;
        #pragma unroll
        for (int kk = 0; kk < 16; kk++) {
            const ull* Bu = (const ull*)(Bs + kk * 256) + tx * 4;
            ull b0 = Bu[0], b1 = Bu[1], b2 = Bu[2], b3 = Bu[3];
            #pragma unroll
            for (int i = 0; i < 8; i++) {
                ull aa = pack2(Ar[i * 256 + kk]);   // warp-broadcast LDS
                fma2(acc[i][0], aa, b0);
                fma2(acc[i][1], aa, b1);
                fma2(acc[i][2], aa, b2);
                fma2(acc[i][3], aa, b3);
            }
        }
        __syncthreads();
    }

    // epilogue: out_s = sigmoid(z) * spike(t), h = tx*4 + j
    #pragma unroll
    for (int i = 0; i < 8; i++) {
        int r = row0 + ty * 8 + i;
        float res[4];
        #pragma unroll
        for (int j = 0; j < 4; j++)
            res[j] = sigmoid_spike(lo32(acc[i][j]), hi32(acc[i][j]));
        *(float4*)(g_outs + (size_t)r * 128 + tx * 4) =
            make_float4(res[0], res[1], res[2], res[3]);
    }
}

// ============================================================================
// Layer 2: rows r in [0, N). A = [out_s[r] | mean(out_s[N+5r .. N+5r+5))]
//   out[r][h] = sigmoid(z2_h) * (t2_h >= 1),  h in [0,64)
// Tile: 64 rows x 128 cols, 256 threads, per-thread 8x4 (2 pairs).
// ============================================================================
extern "C" __global__ void __launch_bounds__(256, 2)
layer2_kernel(float* __restrict__ out)
{
    extern __shared__ float sm[];
    float* As = sm;                // [64][256]
    float* Bs = sm + 64 * 256;     // [16][128]

    const int tid = threadIdx.x;
    const int row0 = blockIdx.x * 64;

    {
        const int m  = tid >> 2;
        const int q4 = (tid & 3) * 8;
        const int r  = row0 + m;
        float* Arow = As + m * 256;
        if (r < Nn) {
            const float4* xs = (const float4*)(g_outs + (size_t)r * 128);
            const float4* n0 = (const float4*)(g_outs + ((size_t)Nn + (size_t)r * 5) * 128);
            #pragma unroll
            for (int i = 0; i < 8; i++) {
                int k4 = q4 + i;
                *(float4*)(Arow + k4 * 4) = xs[k4];
                float4 a = n0[k4], b = n0[32 + k4], c = n0[64 + k4],
                       d = n0[96 + k4], e = n0[128 + k4];
                float4 s;
                s.x = (a.x + b.x + c.x + d.x + e.x) * 0.2f;
                s.y = (a.y + b.y + c.y + d.y + e.y) * 0.2f;
                s.z = (a.z + b.z + c.z + d.z + e.z) * 0.2f;
                s.w = (a.w + b.w + c.w + d.w + e.w) * 0.2f;
                *(float4*)(Arow + 128 + k4 * 4) = s;
            }
        } else {
            float4 zz = make_float4(0.f, 0.f, 0.f, 0.f);
            #pragma unroll
            for (int i = 0; i < 8; i++) {
                int k4 = q4 + i;
                *(float4*)(Arow + k4 * 4) = zz;
                *(float4*)(Arow + 128 + k4 * 4) = zz;
            }
        }
    }

    ull acc[8][2];
    #pragma unroll
    for (int i = 0; i < 8; i++) { acc[i][0] = 0ULL; acc[i][1] = 0ULL; }

    const int ty = tid >> 5;
    const int tx = tid & 31;

    // prefetch B tile 0 (16x128 floats = 512 float4, 2 per thread)
    float4 pre[2];
    {
        const float4* W4 = (const float4*)g_W2c;
        #pragma unroll
        for (int j = 0; j < 2; j++) pre[j] = W4[tid + j * 256];
    }
    __syncthreads();

    for (int kt = 0; kt < 16; kt++) {
        #pragma unroll
        for (int j = 0; j < 2; j++) {
            int lin = tid + j * 256;
            *(float4*)(Bs + lin * 4) = pre[j];
        }
        __syncthreads();
        if (kt + 1 < 16) {
            const float4* W4 = (const float4*)(g_W2c + (kt + 1) * 16 * 128);
            #pragma unroll
            for (int j = 0; j < 2; j++) pre[j] = W4[tid + j * 256];
        }
        const float* Ar = As + ty * 8 * 256 + kt * 16;
        #pragma unroll
        for (int kk = 0; kk < 16; kk++) {
            const ull* Bu = (const ull*)(Bs + kk * 128) + tx * 2;
            ull b0 = Bu[0], b1 = Bu[1];
            #pragma unroll
            for (int i = 0; i < 8; i++) {
                ull aa = pack2(Ar[i * 256 + kk]);
                fma2(acc[i][0], aa, b0);
                fma2(acc[i][1], aa, b1);
            }
        }
        __syncthreads();
    }

    #pragma unroll
    for (int i = 0; i < 8; i++) {
        int r = row0 + ty * 8 + i;
        if (r < Nn) {
            float2 res;
            res.x = sigmoid_spike(lo32(acc[i][0]), hi32(acc[i][0]));
            res.y = sigmoid_spike(lo32(acc[i][1]), hi32(acc[i][1]));
            *(float2*)(out + (size_t)r * 64 + tx * 2) = res;
        }
    }
}

// ============================================================================
extern "C" void kernel_launch(void* const* d_in, const int* in_sizes, int n_in,
                              void* d_out, int out_size)
{
    const float* h0   = (const float*)d_in[0];
    const float* h1   = (const float*)d_in[1];
    const float* h2   = (const float*)d_in[2];
    const float* Wl1  = (const float*)d_in[3];
    const float* Wr1  = (const float*)d_in[4];
    const float* Wlt1 = (const float*)d_in[5];
    const float* Wrt1 = (const float*)d_in[6];
    const float* Wl2  = (const float*)d_in[7];
    const float* Wr2  = (const float*)d_in[8];
    const float* Wlt2 = (const float*)d_in[9];
    const float* Wrt2 = (const float*)d_in[10];
    float* out = (float*)d_out;

    const int smem1 = (64 * 256 + 16 * 256) * 4;   // 81920 B
    const int smem2 = (64 * 256 + 16 * 128) * 4;   // 73728 B
    cudaFuncSetAttribute(layer1_kernel, cudaFuncAttributeMaxDynamicSharedMemorySize, smem1);
    cudaFuncSetAttribute(layer2_kernel, cudaFuncAttributeMaxDynamicSharedMemorySize, smem2);

    prep_kernel<<<256, 256>>>(Wl1, Wr1, Wlt1, Wrt1, Wl2, Wr2, Wlt2, Wrt2);
    layer1_kernel<<<M1ROWS / 64, 256, smem1>>>(h0, h1, h2);
    layer2_kernel<<<(Nn + 63) / 64, 256, smem2>>>(out);
}

// round 4
// speedup vs baseline: 1.3579x; 1.3579x over previous
#include <cuda_runtime.h>
#include <cuda_fp16.h>
#include <cstdint>

#define Nn     100000
#define ROWS1  600000

// ---------------- device scratch (static globals: allocation-free) ----------
__device__ __align__(1024) __half g_W1img[2][2][4][8192];  // [y][comp][chunk][128n x 64k] swizzled
__device__ __align__(1024) __half g_W2img[2][4][8192];     // [comp][chunk][...]
__device__ __align__(128)  float  g_outs[(size_t)ROWS1 * 128];

// ---------------- helpers ---------------------------------------------------
static __device__ __forceinline__ uint32_t smem_u32(const void* p) {
    uint32_t a;
    asm("{ .reg .u64 t; cvta.to.shared.u64 t, %1; cvt.u32.u64 %0, t; }" : "=r"(a) : "l"(p));
    return a;
}
static __device__ __forceinline__ void ldm4(uint32_t* r, uint32_t addr) {
    asm volatile("ldmatrix.sync.aligned.m8n8.x4.shared.b16 {%0,%1,%2,%3}, [%4];"
                 : "=r"(r[0]), "=r"(r[1]), "=r"(r[2]), "=r"(r[3]) : "r"(addr));
}
static __device__ __forceinline__ void mma16816(float* c, const uint32_t* a,
                                                uint32_t b0, uint32_t b1) {
    asm volatile("mma.sync.aligned.m16n8k16.row.col.f32.f16.f16.f32 "
                 "{%0,%1,%2,%3}, {%4,%5,%6,%7}, {%8,%9}, {%0,%1,%2,%3};"
                 : "+f"(c[0]), "+f"(c[1]), "+f"(c[2]), "+f"(c[3])
                 : "r"(a[0]), "r"(a[1]), "r"(a[2]), "r"(a[3]), "r"(b0), "r"(b1));
}
// swizzled byte offset inside a [128row][64k fp16] tile (128B rows, 16B units)
static __device__ __forceinline__ int swz(int row, int unit16) {
    int off = row * 128 + unit16 * 16;
    return off ^ ((off >> 3) & 0x70);
}

// ============================================================================
// prep: split weights fp32 -> (hi, lo) fp16, SW128-swizzled SMEM-image layout.
// Row n of B operand: unit u = n>>1; n even = t-weights, n odd = z-weights.
// ============================================================================
__global__ void prep_kernel(const float* __restrict__ Wl1, const float* __restrict__ Wr1,
                            const float* __restrict__ Wlt1, const float* __restrict__ Wrt1,
                            const float* __restrict__ Wl2, const float* __restrict__ Wr2,
                            const float* __restrict__ Wlt2, const float* __restrict__ Wrt2)
{
    int uid = blockIdx.x * blockDim.x + threadIdx.x;
    if (uid >= 8192 + 4096) return;

    const float *WL, *WR;
    char *hibase, *lobase;
    int v, u, chunk, n, k8;
    if (uid < 8192) {                       // layer 1
        v = uid;
        int y = v >> 12; v &= 4095;
        chunk = v >> 10; v &= 1023;
        n = v >> 3;  k8 = v & 7;
        u = y * 64 + (n >> 1);
        bool zsel = n & 1;
        WL = zsel ? Wl1 : Wlt1;
        WR = zsel ? Wr1 : Wrt1;
        hibase = (char*)&g_W1img[y][0][chunk][0];
        lobase = (char*)&g_W1img[y][1][chunk][0];
    } else {                                // layer 2
        v = uid - 8192;
        chunk = v >> 10; v &= 1023;
        n = v >> 3;  k8 = v & 7;
        u = n >> 1;
        bool zsel = n & 1;
        WL = zsel ? Wl2 : Wlt2;
        WR = zsel ? Wr2 : Wrt2;
        hibase = (char*)&g_W2img[0][chunk][0];
        lobase = (char*)&g_W2img[1][chunk][0];
    }
    int off = n * 128 + k8 * 16;
    off ^= (off >> 3) & 0x70;
    uint32_t hu[4], lu[4];
    #pragma unroll
    for (int j = 0; j < 4; j++) {
        float f0, f1;
        int kg = chunk * 64 + k8 * 8 + 2 * j;
        f0 = (kg < 128) ? WL[u * 128 + kg] : WR[u * 128 + kg - 128];
        kg++;
        f1 = (kg < 128) ? WL[u * 128 + kg] : WR[u * 128 + kg - 128];
        __half h0 = __float2half_rn(f0), h1 = __float2half_rn(f1);
        __half l0 = __float2half_rn(f0 - __half2float(h0));
        __half l1 = __float2half_rn(f1 - __half2float(h1));
        __half2 hp = __halves2half2(h0, h1), lp = __halves2half2(l0, l1);
        hu[j] = *(uint32_t*)&hp; lu[j] = *(uint32_t*)&lp;
    }
    *(uint4*)(hibase + off) = make_uint4(hu[0], hu[1], hu[2], hu[3]);
    *(uint4*)(lobase + off) = make_uint4(lu[0], lu[1], lu[2], lu[3]);
}

// ============================================================================
// Tiled GEMM + epilogue, fp16x3 split on mma.sync (HMMA).
// CTA: 128 rows x 128 cols, 256 threads (8 warps as 2M x 4N, warp tile 64x32).
// SMEM: [SM_B .. +131072)  B resident: [comp][chunk(4)][128n x 64k] fp16 SW128
//       [SM_A .. +65536)   A stages:   [stage(2)][comp][128m x 64k] fp16 SW128
// ============================================================================
#define SM_B   1024
#define SM_A   132096
#define SM_TOT 197632

extern "C" __global__ void __launch_bounds__(256, 1)
signn_tile_kernel(int mode,
                  const float* __restrict__ s0,   // layer1: h0
                  const float* __restrict__ s1,   // layer1: h1
                  const float* __restrict__ s2,   // layer1: h2
                  float* __restrict__ outp)       // layer2: final out
{
    extern __shared__ __align__(1024) char smem[];
    const uint32_t sb = smem_u32(smem);
    const int tid = threadIdx.x, wid = tid >> 5, lane = tid & 31;
    const int y = blockIdx.y;
    const int row0 = blockIdx.x * 128;
    const int nrows = mode ? Nn : ROWS1;

    const float* selfb = s0;
    const float* nbb   = s1;
    if (mode) { selfb = g_outs; nbb = g_outs + (size_t)Nn * 128; }

    // ---- stage B (resident, 128 KB) ----
    {
        const uint4* bsrc = mode ? (const uint4*)&g_W2img[0][0][0]
                                 : (const uint4*)&g_W1img[y][0][0][0];
        uint4* bdst = (uint4*)(smem + SM_B);
        #pragma unroll 8
        for (int i = tid; i < 8192; i += 256) bdst[i] = bsrc[i];
    }

    const int wm = wid & 1;          // M warp group: 64 rows
    const int wn = wid >> 1;         // N warp group: 32 cols
    float acc[64];
    #pragma unroll
    for (int i = 0; i < 64; i++) acc[i] = 0.0f;

    // ldmatrix lane address components (within a 128x64 tile)
    const int lrow = (lane & 7) + ((lane >> 3) & 1) * 8;   // row offset in 16-block
    const int lcol = lane >> 4;                            // 16B-unit offset (0/1)

    // ---- main loop over 4 K-chunks of 64 ----
    for (int c = 0; c < 4; c++) {
        char* Ah = smem + SM_A + ((c & 1) * 2 + 0) * 16384;
        char* Al = smem + SM_A + ((c & 1) * 2 + 1) * 16384;

        // ---- build A chunk: 1024 units = 128 rows x 8 k-octets ----
        for (int t = 0; t < 4; t++) {
            int unit = tid + t * 256;
            int m = unit >> 3, k8 = unit & 7;
            int r = row0 + m;
            float f[8];
            if (r < nrows) {
                if (mode == 0 && r >= Nn) {
                    size_t rr = (size_t)(r - Nn);
                    if (c < 2) {
                        const float* p = s1 + rr * 128 + c * 64 + k8 * 8;
                        float4 a = *(const float4*)p, b = *(const float4*)(p + 4);
                        f[0]=a.x; f[1]=a.y; f[2]=a.z; f[3]=a.w; f[4]=b.x; f[5]=b.y; f[6]=b.z; f[7]=b.w;
                    } else {
                        const float* np = s2 + rr * 256 + (c - 2) * 64 + k8 * 8;
                        float4 a0 = *(const float4*)np,         a1 = *(const float4*)(np + 4);
                        float4 b0 = *(const float4*)(np + 128), b1 = *(const float4*)(np + 132);
                        f[0]=(a0.x+b0.x)*0.5f; f[1]=(a0.y+b0.y)*0.5f; f[2]=(a0.z+b0.z)*0.5f; f[3]=(a0.w+b0.w)*0.5f;
                        f[4]=(a1.x+b1.x)*0.5f; f[5]=(a1.y+b1.y)*0.5f; f[6]=(a1.z+b1.z)*0.5f; f[7]=(a1.w+b1.w)*0.5f;
                    }
                } else {
                    if (c < 2) {
                        const float* p = selfb + (size_t)r * 128 + c * 64 + k8 * 8;
                        float4 a = *(const float4*)p, b = *(const float4*)(p + 4);
                        f[0]=a.x; f[1]=a.y; f[2]=a.z; f[3]=a.w; f[4]=b.x; f[5]=b.y; f[6]=b.z; f[7]=b.w;
                    } else {
                        const float* np = nbb + (size_t)r * 640 + (c - 2) * 64 + k8 * 8;
                        float s[8] = {0,0,0,0,0,0,0,0};
                        #pragma unroll
                        for (int q = 0; q < 5; q++) {
                            float4 a = *(const float4*)(np + q * 128);
                            float4 b = *(const float4*)(np + q * 128 + 4);
                            s[0]+=a.x; s[1]+=a.y; s[2]+=a.z; s[3]+=a.w;
                            s[4]+=b.x; s[5]+=b.y; s[6]+=b.z; s[7]+=b.w;
                        }
                        #pragma unroll
                        for (int q = 0; q < 8; q++) f[q] = s[q] * 0.2f;
                    }
                }
            } else {
                #pragma unroll
                for (int q = 0; q < 8; q++) f[q] = 0.0f;
            }

            uint32_t hu[4], lu[4];
            #pragma unroll
            for (int j = 0; j < 4; j++) {
                float x0 = f[2 * j], x1 = f[2 * j + 1];
                __half h0 = __float2half_rn(x0), h1 = __float2half_rn(x1);
                __half l0 = __float2half_rn(x0 - __half2float(h0));
                __half l1 = __float2half_rn(x1 - __half2float(h1));
                __half2 hp = __halves2half2(h0, h1), lp = __halves2half2(l0, l1);
                hu[j] = *(uint32_t*)&hp; lu[j] = *(uint32_t*)&lp;
            }
            int off = swz(m, k8);   // FIX: octet k8 = 16B unit k8 (was k8*2 -> OOB)
            *(uint4*)(Ah + off) = make_uint4(hu[0], hu[1], hu[2], hu[3]);
            *(uint4*)(Al + off) = make_uint4(lu[0], lu[1], lu[2], lu[3]);
        }
        __syncthreads();

        // ---- HMMA over this chunk: 4 k16 steps ----
        const uint32_t aBase = sb + SM_A + ((c & 1) * 2) * 16384;
        const uint32_t bBase = sb + SM_B + c * 16384;
        #pragma unroll
        for (int kk = 0; kk < 4; kk++) {
            uint32_t AH[4][4], AL[4][4], BH[2][4], BL[2][4];
            #pragma unroll
            for (int mf = 0; mf < 4; mf++) {
                int r = wm * 64 + mf * 16 + lrow;
                int u = kk * 2 + lcol;
                ldm4(AH[mf], aBase + swz(r, u));
                ldm4(AL[mf], aBase + 16384 + swz(r, u));
            }
            #pragma unroll
            for (int nb = 0; nb < 2; nb++) {
                int r = wn * 32 + nb * 16 + lrow;
                int u = kk * 2 + lcol;
                ldm4(BH[nb], bBase + swz(r, u));
                ldm4(BL[nb], bBase + 65536 + swz(r, u));
            }
            #pragma unroll
            for (int mf = 0; mf < 4; mf++)
                #pragma unroll
                for (int nb = 0; nb < 2; nb++)
                    #pragma unroll
                    for (int h = 0; h < 2; h++) {
                        float* cc = acc + mf * 16 + (nb * 2 + h) * 4;
                        mma16816(cc, AH[mf], BH[nb][h], BH[nb][2 + h]);
                        mma16816(cc, AH[mf], BL[nb][h], BL[nb][2 + h]);
                        mma16816(cc, AL[mf], BH[nb][h], BH[nb][2 + h]);
                    }
        }
        __syncthreads();
    }

    // ---- epilogue: out_s = sigmoid(z) * (t >= 1); (t,z) = (n even, n odd) ----
    const int qlane = lane >> 2, tlane = lane & 3;
    #pragma unroll
    for (int mf = 0; mf < 4; mf++) {
        int r0 = row0 + wm * 64 + mf * 16 + qlane;
        #pragma unroll
        for (int nn = 0; nn < 4; nn++) {
            const float* cc = acc + mf * 16 + nn * 4;
            int u = wn * 16 + nn * 4 + tlane;       // unit within this y-half
            #pragma unroll
            for (int rr = 0; rr < 2; rr++) {
                int r = r0 + rr * 8;
                if (r < nrows) {
                    float tt = cc[rr * 2 + 0], zz = cc[rr * 2 + 1];
                    float o = (tt >= 1.0f) ? (1.0f / (1.0f + __expf(-zz))) : 0.0f;
                    if (mode) outp[(size_t)r * 64 + u] = o;
                    else      g_outs[(size_t)r * 128 + y * 64 + u] = o;
                }
            }
        }
    }
}

// ============================================================================
extern "C" void kernel_launch(void* const* d_in, const int* in_sizes, int n_in,
                              void* d_out, int out_size)
{
    const float* h0   = (const float*)d_in[0];
    const float* h1   = (const float*)d_in[1];
    const float* h2   = (const float*)d_in[2];
    const float* Wl1  = (const float*)d_in[3];
    const float* Wr1  = (const float*)d_in[4];
    const float* Wlt1 = (const float*)d_in[5];
    const float* Wrt1 = (const float*)d_in[6];
    const float* Wl2  = (const float*)d_in[7];
    const float* Wr2  = (const float*)d_in[8];
    const float* Wlt2 = (const float*)d_in[9];
    const float* Wrt2 = (const float*)d_in[10];
    float* out = (float*)d_out;

    cudaFuncSetAttribute(signn_tile_kernel,
                         cudaFuncAttributeMaxDynamicSharedMemorySize, SM_TOT);

    prep_kernel<<<48, 256>>>(Wl1, Wr1, Wlt1, Wrt1, Wl2, Wr2, Wlt2, Wrt2);

    dim3 g1((ROWS1 + 127) / 128, 2);
    signn_tile_kernel<<<g1, 256, SM_TOT>>>(0, h0, h1, h2, nullptr);

    dim3 g2((Nn + 127) / 128, 1);
    signn_tile_kernel<<<g2, 256, SM_TOT>>>(1, nullptr, nullptr, nullptr, out);
}

// round 5
// speedup vs baseline: 1.8342x; 1.3508x over previous
#include <cuda_runtime.h>
#include <cuda_fp16.h>
#include <cstdint>

#define Nn     100000
#define ROWS1  600000

// ---------------- device scratch (static globals: allocation-free) ----------
__device__ __align__(1024) __half g_W1img[2][2][4][8192];  // [y][comp][chunk][128n x 64k] swizzled
__device__ __align__(1024) __half g_W2img[2][4][8192];     // [comp][chunk][...]
__device__ __align__(128)  float  g_outs[(size_t)ROWS1 * 128];
__device__ __align__(128)  float  g_means[(size_t)ROWS1 * 128];

// ---------------- helpers ---------------------------------------------------
static __device__ __forceinline__ uint32_t smem_u32(const void* p) {
    uint32_t a;
    asm("{ .reg .u64 t; cvta.to.shared.u64 t, %1; cvt.u32.u64 %0, t; }" : "=r"(a) : "l"(p));
    return a;
}
static __device__ __forceinline__ void ldm4(uint32_t* r, uint32_t addr) {
    asm volatile("ldmatrix.sync.aligned.m8n8.x4.shared.b16 {%0,%1,%2,%3}, [%4];"
                 : "=r"(r[0]), "=r"(r[1]), "=r"(r[2]), "=r"(r[3]) : "r"(addr));
}
static __device__ __forceinline__ void mma16816(float* c, const uint32_t* a,
                                                uint32_t b0, uint32_t b1) {
    asm volatile("mma.sync.aligned.m16n8k16.row.col.f32.f16.f16.f32 "
                 "{%0,%1,%2,%3}, {%4,%5,%6,%7}, {%8,%9}, {%0,%1,%2,%3};"
                 : "+f"(c[0]), "+f"(c[1]), "+f"(c[2]), "+f"(c[3])
                 : "r"(a[0]), "r"(a[1]), "r"(a[2]), "r"(a[3]), "r"(b0), "r"(b1));
}
// swizzled byte offset inside a [128row][64k fp16] tile (128B rows, 16B units)
static __device__ __forceinline__ int swz(int row, int unit16) {
    int off = row * 128 + unit16 * 16;
    return off ^ ((off >> 3) & 0x70);
}

// ============================================================================
// prep: split weights fp32 -> (hi, lo) fp16, SW128-swizzled SMEM-image layout.
// Row n of B operand: unit u = n>>1; n even = t-weights, n odd = z-weights.
// ============================================================================
__global__ void prep_kernel(const float* __restrict__ Wl1, const float* __restrict__ Wr1,
                            const float* __restrict__ Wlt1, const float* __restrict__ Wrt1,
                            const float* __restrict__ Wl2, const float* __restrict__ Wr2,
                            const float* __restrict__ Wlt2, const float* __restrict__ Wrt2)
{
    int uid = blockIdx.x * blockDim.x + threadIdx.x;
    if (uid >= 8192 + 4096) return;

    const float *WL, *WR;
    char *hibase, *lobase;
    int v, u, chunk, n, k8;
    if (uid < 8192) {                       // layer 1
        v = uid;
        int y = v >> 12; v &= 4095;
        chunk = v >> 10; v &= 1023;
        n = v >> 3;  k8 = v & 7;
        u = y * 64 + (n >> 1);
        bool zsel = n & 1;
        WL = zsel ? Wl1 : Wlt1;
        WR = zsel ? Wr1 : Wrt1;
        hibase = (char*)&g_W1img[y][0][chunk][0];
        lobase = (char*)&g_W1img[y][1][chunk][0];
    } else {                                // layer 2
        v = uid - 8192;
        chunk = v >> 10; v &= 1023;
        n = v >> 3;  k8 = v & 7;
        u = n >> 1;
        bool zsel = n & 1;
        WL = zsel ? Wl2 : Wlt2;
        WR = zsel ? Wr2 : Wrt2;
        hibase = (char*)&g_W2img[0][chunk][0];
        lobase = (char*)&g_W2img[1][chunk][0];
    }
    int off = n * 128 + k8 * 16;
    off ^= (off >> 3) & 0x70;
    uint32_t hu[4], lu[4];
    #pragma unroll
    for (int j = 0; j < 4; j++) {
        float f0, f1;
        int kg = chunk * 64 + k8 * 8 + 2 * j;
        f0 = (kg < 128) ? WL[u * 128 + kg] : WR[u * 128 + kg - 128];
        kg++;
        f1 = (kg < 128) ? WL[u * 128 + kg] : WR[u * 128 + kg - 128];
        __half h0 = __float2half_rn(f0), h1 = __float2half_rn(f1);
        __half l0 = __float2half_rn(f0 - __half2float(h0));
        __half l1 = __float2half_rn(f1 - __half2float(h1));
        __half2 hp = __halves2half2(h0, h1), lp = __halves2half2(l0, l1);
        hu[j] = *(uint32_t*)&hp; lu[j] = *(uint32_t*)&lp;
    }
    *(uint4*)(hibase + off) = make_uint4(hu[0], hu[1], hu[2], hu[3]);
    *(uint4*)(lobase + off) = make_uint4(lu[0], lu[1], lu[2], lu[3]);
}

// ============================================================================
// mean1: g_means[r] = (r<Nn) ? mean of 5 h1 rows : mean of 2 h2 rows
// ============================================================================
__global__ void mean1_kernel(const float* __restrict__ h1, const float* __restrict__ h2)
{
    int idx = blockIdx.x * blockDim.x + threadIdx.x;
    if (idx >= ROWS1 * 32) return;
    int r = idx >> 5, j = idx & 31;
    float4 s;
    if (r < Nn) {
        const float4* p = (const float4*)(h1 + (size_t)r * 640) + j;
        float4 a = p[0], b = p[32], c = p[64], d = p[96], e = p[128];
        s.x = (a.x + b.x + c.x + d.x + e.x) * 0.2f;
        s.y = (a.y + b.y + c.y + d.y + e.y) * 0.2f;
        s.z = (a.z + b.z + c.z + d.z + e.z) * 0.2f;
        s.w = (a.w + b.w + c.w + d.w + e.w) * 0.2f;
    } else {
        const float4* p = (const float4*)(h2 + (size_t)(r - Nn) * 256) + j;
        float4 a = p[0], b = p[32];
        s.x = (a.x + b.x) * 0.5f;
        s.y = (a.y + b.y) * 0.5f;
        s.z = (a.z + b.z) * 0.5f;
        s.w = (a.w + b.w) * 0.5f;
    }
    *((float4*)(g_means + (size_t)r * 128) + j) = s;
}

// mean for layer 2: g_means[r] = mean of 5 g_outs rows (h1p block)
__global__ void mean2_kernel()
{
    int idx = blockIdx.x * blockDim.x + threadIdx.x;
    if (idx >= Nn * 32) return;
    int r = idx >> 5, j = idx & 31;
    const float4* p = (const float4*)(g_outs + ((size_t)Nn + (size_t)r * 5) * 128) + j;
    float4 a = p[0], b = p[32], c = p[64], d = p[96], e = p[128];
    float4 s;
    s.x = (a.x + b.x + c.x + d.x + e.x) * 0.2f;
    s.y = (a.y + b.y + c.y + d.y + e.y) * 0.2f;
    s.z = (a.z + b.z + c.z + d.z + e.z) * 0.2f;
    s.w = (a.w + b.w + c.w + d.w + e.w) * 0.2f;
    *((float4*)(g_means + (size_t)r * 128) + j) = s;
}

// ============================================================================
// fetch 8 float4 for one K-chunk (register prefetch)
// ============================================================================
static __device__ __forceinline__ void fetch8(float4* dst, int mode, int c,
                                              int row0, int tid, int nrows,
                                              const float* __restrict__ h0,
                                              const float* __restrict__ h1)
{
    const int k8 = tid & 7;
    #pragma unroll
    for (int t = 0; t < 4; t++) {
        int m = (tid >> 3) + t * 32;
        int r = row0 + m;
        if (r < nrows) {
            const float* p;
            if (c < 2) {
                const float* selfp = mode
                    ? g_outs + (size_t)r * 128
                    : ((r < Nn) ? h0 + (size_t)r * 128 : h1 + (size_t)(r - Nn) * 128);
                p = selfp + c * 64 + k8 * 8;
            } else {
                p = g_means + (size_t)r * 128 + (c - 2) * 64 + k8 * 8;
            }
            dst[2 * t]     = *(const float4*)p;
            dst[2 * t + 1] = *(const float4*)(p + 4);
        } else {
            dst[2 * t] = dst[2 * t + 1] = make_float4(0.f, 0.f, 0.f, 0.f);
        }
    }
}

static __device__ __forceinline__ void cvt_store(const float4* src, char* Ah, char* Al, int tid)
{
    const int k8 = tid & 7;
    #pragma unroll
    for (int t = 0; t < 4; t++) {
        int m = (tid >> 3) + t * 32;
        float f[8];
        f[0] = src[2*t].x; f[1] = src[2*t].y; f[2] = src[2*t].z; f[3] = src[2*t].w;
        f[4] = src[2*t+1].x; f[5] = src[2*t+1].y; f[6] = src[2*t+1].z; f[7] = src[2*t+1].w;
        uint32_t hu[4], lu[4];
        #pragma unroll
        for (int j = 0; j < 4; j++) {
            float x0 = f[2*j], x1 = f[2*j+1];
            __half h0 = __float2half_rn(x0), h1 = __float2half_rn(x1);
            __half l0 = __float2half_rn(x0 - __half2float(h0));
            __half l1 = __float2half_rn(x1 - __half2float(h1));
            __half2 hp = __halves2half2(h0, h1), lp = __halves2half2(l0, l1);
            hu[j] = *(uint32_t*)&hp; lu[j] = *(uint32_t*)&lp;
        }
        int off = swz(m, k8);
        *(uint4*)(Ah + off) = make_uint4(hu[0], hu[1], hu[2], hu[3]);
        *(uint4*)(Al + off) = make_uint4(lu[0], lu[1], lu[2], lu[3]);
    }
}

// ============================================================================
// Tiled GEMM + epilogue, fp16x3 split on mma.sync (HMMA), register-prefetch
// pipelined A build. CTA: 128 rows x 128 cols, 256 threads (2M x 4N warps).
// SMEM: [SM_B..+131072) B resident [comp][chunk(4)][128n x 64k] fp16 SW128
//       [SM_A..+32768)  A tile (single stage) [comp][128m x 64k] fp16 SW128
// ============================================================================
#define SM_B   1024
#define SM_A   132096
#define SM_TOT 164864

extern "C" __global__ void __launch_bounds__(256, 1)
signn_tile_kernel(int mode,
                  const float* __restrict__ h0,
                  const float* __restrict__ h1,
                  float* __restrict__ outp)
{
    extern __shared__ __align__(1024) char smem[];
    const uint32_t sb = smem_u32(smem);
    const int tid = threadIdx.x, wid = tid >> 5, lane = tid & 31;
    const int y = blockIdx.x;                 // N-half (layer1: 0/1; layer2: 0)
    const int row0 = blockIdx.y * 128;
    const int nrows = mode ? Nn : ROWS1;

    // ---- stage B (resident, 128 KB) ----
    {
        const uint4* bsrc = mode ? (const uint4*)&g_W2img[0][0][0]
                                 : (const uint4*)&g_W1img[y][0][0][0];
        uint4* bdst = (uint4*)(smem + SM_B);
        #pragma unroll 8
        for (int i = tid; i < 8192; i += 256) bdst[i] = bsrc[i];
    }

    const int wm = wid & 1;          // M warp group: 64 rows
    const int wn = wid >> 1;         // N warp group: 32 cols
    float acc[64];
    #pragma unroll
    for (int i = 0; i < 64; i++) acc[i] = 0.0f;

    const int lrow = (lane & 7) + ((lane >> 3) & 1) * 8;
    const int lcol = lane >> 4;

    char* Ah = smem + SM_A;
    char* Al = smem + SM_A + 16384;
    const uint32_t aBase = sb + SM_A;

    float4 pre[2][8];
    fetch8(pre[0], mode, 0, row0, tid, nrows, h0, h1);

    #pragma unroll
    for (int c = 0; c < 4; c++) {
        if (c < 3) fetch8(pre[(c + 1) & 1], mode, c + 1, row0, tid, nrows, h0, h1);

        __syncthreads();                     // previous MMA finished reading A tile
        cvt_store(pre[c & 1], Ah, Al, tid);
        __syncthreads();                     // A tile (and for c=0, B) ready

        const uint32_t bBase = sb + SM_B + c * 16384;
        #pragma unroll
        for (int kk = 0; kk < 4; kk++) {
            uint32_t AH[4][4], AL[4][4], BH[2][4], BL[2][4];
            #pragma unroll
            for (int mf = 0; mf < 4; mf++) {
                int r = wm * 64 + mf * 16 + lrow;
                int u = kk * 2 + lcol;
                ldm4(AH[mf], aBase + swz(r, u));
                ldm4(AL[mf], aBase + 16384 + swz(r, u));
            }
            #pragma unroll
            for (int nb = 0; nb < 2; nb++) {
                int r = wn * 32 + nb * 16 + lrow;
                int u = kk * 2 + lcol;
                ldm4(BH[nb], bBase + swz(r, u));
                ldm4(BL[nb], bBase + 65536 + swz(r, u));
            }
            #pragma unroll
            for (int mf = 0; mf < 4; mf++)
                #pragma unroll
                for (int nb = 0; nb < 2; nb++)
                    #pragma unroll
                    for (int h = 0; h < 2; h++) {
                        float* cc = acc + mf * 16 + (nb * 2 + h) * 4;
                        mma16816(cc, AH[mf], BH[nb][h], BH[nb][2 + h]);
                        mma16816(cc, AH[mf], BL[nb][h], BL[nb][2 + h]);
                        mma16816(cc, AL[mf], BH[nb][h], BH[nb][2 + h]);
                    }
        }
    }

    // ---- epilogue: out = sigmoid(z) * (t >= 1); (t,z) = (n even, n odd) ----
    const int qlane = lane >> 2, tlane = lane & 3;
    #pragma unroll
    for (int mf = 0; mf < 4; mf++) {
        int r0 = row0 + wm * 64 + mf * 16 + qlane;
        #pragma unroll
        for (int nn = 0; nn < 4; nn++) {
            const float* cc = acc + mf * 16 + nn * 4;
            int u = wn * 16 + nn * 4 + tlane;
            #pragma unroll
            for (int rr = 0; rr < 2; rr++) {
                int r = r0 + rr * 8;
                if (r < nrows) {
                    float tt = cc[rr * 2 + 0], zz = cc[rr * 2 + 1];
                    float o = (tt >= 1.0f) ? (1.0f / (1.0f + __expf(-zz))) : 0.0f;
                    if (mode) outp[(size_t)r * 64 + u] = o;
                    else      g_outs[(size_t)r * 128 + y * 64 + u] = o;
                }
            }
        }
    }
}

// ============================================================================
extern "C" void kernel_launch(void* const* d_in, const int* in_sizes, int n_in,
                              void* d_out, int out_size)
{
    const float* h0   = (const float*)d_in[0];
    const float* h1   = (const float*)d_in[1];
    const float* h2   = (const float*)d_in[2];
    const float* Wl1  = (const float*)d_in[3];
    const float* Wr1  = (const float*)d_in[4];
    const float* Wlt1 = (const float*)d_in[5];
    const float* Wrt1 = (const float*)d_in[6];
    const float* Wl2  = (const float*)d_in[7];
    const float* Wr2  = (const float*)d_in[8];
    const float* Wlt2 = (const float*)d_in[9];
    const float* Wrt2 = (const float*)d_in[10];
    float* out = (float*)d_out;

    cudaFuncSetAttribute(signn_tile_kernel,
                         cudaFuncAttributeMaxDynamicSharedMemorySize, SM_TOT);

    prep_kernel<<<48, 256>>>(Wl1, Wr1, Wlt1, Wrt1, Wl2, Wr2, Wlt2, Wrt2);
    mean1_kernel<<<(ROWS1 * 32 + 255) / 256, 256>>>(h1, h2);

    dim3 g1(2, (ROWS1 + 127) / 128);           // x = N-half (adjacent -> L2 reuse)
    signn_tile_kernel<<<g1, 256, SM_TOT>>>(0, h0, h1, nullptr);

    mean2_kernel<<<(Nn * 32 + 255) / 256, 256>>>();

    dim3 g2(1, (Nn + 127) / 128);
    signn_tile_kernel<<<g2, 256, SM_TOT>>>(1, nullptr, nullptr, out);
}

// round 6
// speedup vs baseline: 1.8870x; 1.0288x over previous
#include <cuda_runtime.h>
#include <cuda_fp16.h>
#include <cstdint>

#define Nn     100000
#define ROWS1  600000

// ---------------- device scratch (static globals: allocation-free) ----------
__device__ __align__(1024) __half g_W1img[2][2][4][8192];  // [y][comp][chunk][128n x 64k] swizzled
__device__ __align__(1024) __half g_W2img[2][4][8192];     // [comp][chunk][...]
__device__ __align__(128)  float  g_outs[(size_t)ROWS1 * 128];
__device__ __align__(128)  float  g_means[(size_t)ROWS1 * 128];

// ---------------- helpers ---------------------------------------------------
static __device__ __forceinline__ uint32_t smem_u32(const void* p) {
    uint32_t a;
    asm("{ .reg .u64 t; cvta.to.shared.u64 t, %1; cvt.u32.u64 %0, t; }" : "=r"(a) : "l"(p));
    return a;
}
static __device__ __forceinline__ void ldm4(uint32_t* r, uint32_t addr) {
    asm volatile("ldmatrix.sync.aligned.m8n8.x4.shared.b16 {%0,%1,%2,%3}, [%4];"
                 : "=r"(r[0]), "=r"(r[1]), "=r"(r[2]), "=r"(r[3]) : "r"(addr));
}
static __device__ __forceinline__ void mma16816(float* c, const uint32_t* a,
                                                uint32_t b0, uint32_t b1) {
    asm volatile("mma.sync.aligned.m16n8k16.row.col.f32.f16.f16.f32 "
                 "{%0,%1,%2,%3}, {%4,%5,%6,%7}, {%8,%9}, {%0,%1,%2,%3};"
                 : "+f"(c[0]), "+f"(c[1]), "+f"(c[2]), "+f"(c[3])
                 : "r"(a[0]), "r"(a[1]), "r"(a[2]), "r"(a[3]), "r"(b0), "r"(b1));
}
// swizzled byte offset inside a [128row][64k fp16] tile (128B rows, 16B units)
static __device__ __forceinline__ int swz(int row, int unit16) {
    int off = row * 128 + unit16 * 16;
    return off ^ ((off >> 3) & 0x70);
}

// ============================================================================
// prep: split weights fp32 -> (hi, lo) fp16, SW128-swizzled SMEM-image layout.
// ============================================================================
__global__ void prep_kernel(const float* __restrict__ Wl1, const float* __restrict__ Wr1,
                            const float* __restrict__ Wlt1, const float* __restrict__ Wrt1,
                            const float* __restrict__ Wl2, const float* __restrict__ Wr2,
                            const float* __restrict__ Wlt2, const float* __restrict__ Wrt2)
{
    int uid = blockIdx.x * blockDim.x + threadIdx.x;
    if (uid >= 8192 + 4096) return;

    const float *WL, *WR;
    char *hibase, *lobase;
    int v, u, chunk, n, k8;
    if (uid < 8192) {                       // layer 1
        v = uid;
        int y = v >> 12; v &= 4095;
        chunk = v >> 10; v &= 1023;
        n = v >> 3;  k8 = v & 7;
        u = y * 64 + (n >> 1);
        bool zsel = n & 1;
        WL = zsel ? Wl1 : Wlt1;
        WR = zsel ? Wr1 : Wrt1;
        hibase = (char*)&g_W1img[y][0][chunk][0];
        lobase = (char*)&g_W1img[y][1][chunk][0];
    } else {                                // layer 2
        v = uid - 8192;
        chunk = v >> 10; v &= 1023;
        n = v >> 3;  k8 = v & 7;
        u = n >> 1;
        bool zsel = n & 1;
        WL = zsel ? Wl2 : Wlt2;
        WR = zsel ? Wr2 : Wrt2;
        hibase = (char*)&g_W2img[0][chunk][0];
        lobase = (char*)&g_W2img[1][chunk][0];
    }
    int off = n * 128 + k8 * 16;
    off ^= (off >> 3) & 0x70;
    uint32_t hu[4], lu[4];
    #pragma unroll
    for (int j = 0; j < 4; j++) {
        float f0, f1;
        int kg = chunk * 64 + k8 * 8 + 2 * j;
        f0 = (kg < 128) ? WL[u * 128 + kg] : WR[u * 128 + kg - 128];
        kg++;
        f1 = (kg < 128) ? WL[u * 128 + kg] : WR[u * 128 + kg - 128];
        __half h0 = __float2half_rn(f0), h1 = __float2half_rn(f1);
        __half l0 = __float2half_rn(f0 - __half2float(h0));
        __half l1 = __float2half_rn(f1 - __half2float(h1));
        __half2 hp = __halves2half2(h0, h1), lp = __halves2half2(l0, l1);
        hu[j] = *(uint32_t*)&hp; lu[j] = *(uint32_t*)&lp;
    }
    *(uint4*)(hibase + off) = make_uint4(hu[0], hu[1], hu[2], hu[3]);
    *(uint4*)(lobase + off) = make_uint4(lu[0], lu[1], lu[2], lu[3]);
}

// ============================================================================
// mean1: g_means[r] = (r<Nn) ? mean of 5 h1 rows : mean of 2 h2 rows
// ============================================================================
__global__ void mean1_kernel(const float* __restrict__ h1, const float* __restrict__ h2)
{
    int idx = blockIdx.x * blockDim.x + threadIdx.x;
    if (idx >= ROWS1 * 32) return;
    int r = idx >> 5, j = idx & 31;
    float4 s;
    if (r < Nn) {
        const float4* p = (const float4*)(h1 + (size_t)r * 640) + j;
        float4 a = p[0], b = p[32], c = p[64], d = p[96], e = p[128];
        s.x = (a.x + b.x + c.x + d.x + e.x) * 0.2f;
        s.y = (a.y + b.y + c.y + d.y + e.y) * 0.2f;
        s.z = (a.z + b.z + c.z + d.z + e.z) * 0.2f;
        s.w = (a.w + b.w + c.w + d.w + e.w) * 0.2f;
    } else {
        const float4* p = (const float4*)(h2 + (size_t)(r - Nn) * 256) + j;
        float4 a = p[0], b = p[32];
        s.x = (a.x + b.x) * 0.5f;
        s.y = (a.y + b.y) * 0.5f;
        s.z = (a.z + b.z) * 0.5f;
        s.w = (a.w + b.w) * 0.5f;
    }
    *((float4*)(g_means + (size_t)r * 128) + j) = s;
}

// mean for layer 2: g_means[r] = mean of 5 g_outs rows (h1p block)
__global__ void mean2_kernel()
{
    int idx = blockIdx.x * blockDim.x + threadIdx.x;
    if (idx >= Nn * 32) return;
    int r = idx >> 5, j = idx & 31;
    const float4* p = (const float4*)(g_outs + ((size_t)Nn + (size_t)r * 5) * 128) + j;
    float4 a = p[0], b = p[32], c = p[64], d = p[96], e = p[128];
    float4 s;
    s.x = (a.x + b.x + c.x + d.x + e.x) * 0.2f;
    s.y = (a.y + b.y + c.y + d.y + e.y) * 0.2f;
    s.z = (a.z + b.z + c.z + d.z + e.z) * 0.2f;
    s.w = (a.w + b.w + c.w + d.w + e.w) * 0.2f;
    *((float4*)(g_means + (size_t)r * 128) + j) = s;
}

// ============================================================================
// fetch 8 float4 for one K-chunk (register prefetch)
// ============================================================================
static __device__ __forceinline__ void fetch8(float4* dst, int mode, int c,
                                              int row0, int tid, int nrows,
                                              const float* __restrict__ h0,
                                              const float* __restrict__ h1)
{
    const int k8 = tid & 7;
    #pragma unroll
    for (int t = 0; t < 4; t++) {
        int m = (tid >> 3) + t * 32;
        int r = row0 + m;
        if (r < nrows) {
            const float* p;
            if (c < 2) {
                const float* selfp = mode
                    ? g_outs + (size_t)r * 128
                    : ((r < Nn) ? h0 + (size_t)r * 128 : h1 + (size_t)(r - Nn) * 128);
                p = selfp + c * 64 + k8 * 8;
            } else {
                p = g_means + (size_t)r * 128 + (c - 2) * 64 + k8 * 8;
            }
            dst[2 * t]     = *(const float4*)p;
            dst[2 * t + 1] = *(const float4*)(p + 4);
        } else {
            dst[2 * t] = dst[2 * t + 1] = make_float4(0.f, 0.f, 0.f, 0.f);
        }
    }
}

static __device__ __forceinline__ void cvt_store(const float4* src, char* Ah, char* Al, int tid)
{
    const int k8 = tid & 7;
    #pragma unroll
    for (int t = 0; t < 4; t++) {
        int m = (tid >> 3) + t * 32;
        float f[8];
        f[0] = src[2*t].x; f[1] = src[2*t].y; f[2] = src[2*t].z; f[3] = src[2*t].w;
        f[4] = src[2*t+1].x; f[5] = src[2*t+1].y; f[6] = src[2*t+1].z; f[7] = src[2*t+1].w;
        uint32_t hu[4], lu[4];
        #pragma unroll
        for (int j = 0; j < 4; j++) {
            float x0 = f[2*j], x1 = f[2*j+1];
            __half h0 = __float2half_rn(x0), h1 = __float2half_rn(x1);
            __half l0 = __float2half_rn(x0 - __half2float(h0));
            __half l1 = __float2half_rn(x1 - __half2float(h1));
            __half2 hp = __halves2half2(h0, h1), lp = __halves2half2(l0, l1);
            hu[j] = *(uint32_t*)&hp; lu[j] = *(uint32_t*)&lp;
        }
        int off = swz(m, k8);
        *(uint4*)(Ah + off) = make_uint4(hu[0], hu[1], hu[2], hu[3]);
        *(uint4*)(Al + off) = make_uint4(lu[0], lu[1], lu[2], lu[3]);
    }
}

// ============================================================================
// PERSISTENT tiled GEMM + epilogue, fp16x3 split on mma.sync (HMMA).
// Each CTA: one N-half (y), many 128-row tiles; B staged ONCE per CTA.
// Register A-prefetch pipelined across chunk AND tile boundaries.
// SMEM: [SM_B..+131072) B resident [comp][chunk(4)][128n x 64k] fp16 SW128
//       [SM_A..+32768)  A tile (single stage) [comp][128m x 64k] fp16 SW128
// ============================================================================
#define SM_B   1024
#define SM_A   132096
#define SM_TOT 164864

extern "C" __global__ void __launch_bounds__(256, 1)
signn_tile_kernel(int mode,
                  const float* __restrict__ h0,
                  const float* __restrict__ h1,
                  float* __restrict__ outp)
{
    extern __shared__ __align__(1024) char smem[];
    const uint32_t sb = smem_u32(smem);
    const int tid = threadIdx.x, wid = tid >> 5, lane = tid & 31;
    const int y = blockIdx.x;                 // N-half (layer1: 0/1; layer2: 0)
    const int nrows = mode ? Nn : ROWS1;
    const int ntiles = (nrows + 127) >> 7;
    const int stride = gridDim.y;             // tiles advance by #CTAs per y

    // ---- stage B once (resident, 128 KB) ----
    {
        const uint4* bsrc = mode ? (const uint4*)&g_W2img[0][0][0]
                                 : (const uint4*)&g_W1img[y][0][0][0];
        uint4* bdst = (uint4*)(smem + SM_B);
        #pragma unroll 8
        for (int i = tid; i < 8192; i += 256) bdst[i] = bsrc[i];
    }

    const int wm = wid & 1;          // M warp group: 64 rows
    const int wn = wid >> 1;         // N warp group: 32 cols
    const int lrow = (lane & 7) + ((lane >> 3) & 1) * 8;
    const int lcol = lane >> 4;

    char* Ah = smem + SM_A;
    char* Al = smem + SM_A + 16384;
    const uint32_t aBase = sb + SM_A;

    float4 pre[2][8];
    int tile0 = blockIdx.y;
    if (tile0 < ntiles)
        fetch8(pre[0], mode, 0, tile0 * 128, tid, nrows, h0, h1);

    for (int t = tile0; t < ntiles; t += stride) {
        const int row0 = t * 128;
        float acc[64];
        #pragma unroll
        for (int i = 0; i < 64; i++) acc[i] = 0.0f;

        #pragma unroll
        for (int c = 0; c < 4; c++) {
            // prefetch next job: (t, c+1) or (t+stride, 0)
            if (c < 3) {
                fetch8(pre[(c + 1) & 1], mode, c + 1, row0, tid, nrows, h0, h1);
            } else if (t + stride < ntiles) {
                fetch8(pre[(c + 1) & 1], mode, 0, (t + stride) * 128, tid, nrows, h0, h1);
            }

            __syncthreads();                 // previous MMA done reading A tile
            cvt_store(pre[c & 1], Ah, Al, tid);
            __syncthreads();                 // A tile ready (and B on first iter)

            const uint32_t bBase = sb + SM_B + c * 16384;
            #pragma unroll
            for (int kk = 0; kk < 4; kk++) {
                uint32_t AH[4][4], AL[4][4], BH[2][4], BL[2][4];
                #pragma unroll
                for (int mf = 0; mf < 4; mf++) {
                    int r = wm * 64 + mf * 16 + lrow;
                    int u = kk * 2 + lcol;
                    ldm4(AH[mf], aBase + swz(r, u));
                    ldm4(AL[mf], aBase + 16384 + swz(r, u));
                }
                #pragma unroll
                for (int nb = 0; nb < 2; nb++) {
                    int r = wn * 32 + nb * 16 + lrow;
                    int u = kk * 2 + lcol;
                    ldm4(BH[nb], bBase + swz(r, u));
                    ldm4(BL[nb], bBase + 65536 + swz(r, u));
                }
                #pragma unroll
                for (int mf = 0; mf < 4; mf++)
                    #pragma unroll
                    for (int nb = 0; nb < 2; nb++)
                        #pragma unroll
                        for (int h = 0; h < 2; h++) {
                            float* cc = acc + mf * 16 + (nb * 2 + h) * 4;
                            mma16816(cc, AH[mf], BH[nb][h], BH[nb][2 + h]);
                            mma16816(cc, AH[mf], BL[nb][h], BL[nb][2 + h]);
                            mma16816(cc, AL[mf], BH[nb][h], BH[nb][2 + h]);
                        }
            }
        }

        // ---- epilogue: out = sigmoid(z) * (t >= 1); (t,z) = (n even, n odd) ----
        const int qlane = lane >> 2, tlane = lane & 3;
        #pragma unroll
        for (int mf = 0; mf < 4; mf++) {
            int r0 = row0 + wm * 64 + mf * 16 + qlane;
            #pragma unroll
            for (int nn = 0; nn < 4; nn++) {
                const float* cc = acc + mf * 16 + nn * 4;
                int u = wn * 16 + nn * 4 + tlane;
                #pragma unroll
                for (int rr = 0; rr < 2; rr++) {
                    int r = r0 + rr * 8;
                    if (r < nrows) {
                        float tt = cc[rr * 2 + 0], zz = cc[rr * 2 + 1];
                        float o = (tt >= 1.0f) ? (1.0f / (1.0f + __expf(-zz))) : 0.0f;
                        if (mode) outp[(size_t)r * 64 + u] = o;
                        else      g_outs[(size_t)r * 128 + y * 64 + u] = o;
                    }
                }
            }
        }
    }
}

// ============================================================================
extern "C" void kernel_launch(void* const* d_in, const int* in_sizes, int n_in,
                              void* d_out, int out_size)
{
    const float* h0   = (const float*)d_in[0];
    const float* h1   = (const float*)d_in[1];
    const float* h2   = (const float*)d_in[2];
    const float* Wl1  = (const float*)d_in[3];
    const float* Wr1  = (const float*)d_in[4];
    const float* Wlt1 = (const float*)d_in[5];
    const float* Wrt1 = (const float*)d_in[6];
    const float* Wl2  = (const float*)d_in[7];
    const float* Wr2  = (const float*)d_in[8];
    const float* Wlt2 = (const float*)d_in[9];
    const float* Wrt2 = (const float*)d_in[10];
    float* out = (float*)d_out;

    cudaFuncSetAttribute(signn_tile_kernel,
                         cudaFuncAttributeMaxDynamicSharedMemorySize, SM_TOT);

    prep_kernel<<<48, 256>>>(Wl1, Wr1, Wlt1, Wrt1, Wl2, Wr2, Wlt2, Wrt2);
    mean1_kernel<<<(ROWS1 * 32 + 255) / 256, 256>>>(h1, h2);

    dim3 g1(2, 74);                    // 148 persistent CTAs: one y-half each
    signn_tile_kernel<<<g1, 256, SM_TOT>>>(0, h0, h1, nullptr);

    mean2_kernel<<<(Nn * 32 + 255) / 256, 256>>>();

    dim3 g2(1, 148);                   // 148 persistent CTAs
    signn_tile_kernel<<<g2, 256, SM_TOT>>>(1, nullptr, nullptr, out);
}

// round 7
// speedup vs baseline: 2.1385x; 1.1333x over previous
#include <cuda_runtime.h>
#include <cuda_fp16.h>
#include <cstdint>

#define Nn     100000
#define ROWS1  600000

// ---------------- device scratch (static globals: allocation-free) ----------
__device__ __align__(1024) __half g_W1img[2][2][4][8192];  // [y][comp][chunk][128n x 64k] swizzled
__device__ __align__(1024) __half g_W2img[2][4][8192];     // [comp][chunk][...]
__device__ __align__(128)  float  g_outs[(size_t)ROWS1 * 128];
__device__ __align__(128)  float  g_means[(size_t)ROWS1 * 128];

// ---------------- helpers ---------------------------------------------------
static __device__ __forceinline__ uint32_t smem_u32(const void* p) {
    uint32_t a;
    asm("{ .reg .u64 t; cvta.to.shared.u64 t, %1; cvt.u32.u64 %0, t; }" : "=r"(a) : "l"(p));
    return a;
}
static __device__ __forceinline__ void ldm4(uint32_t* r, uint32_t addr) {
    asm volatile("ldmatrix.sync.aligned.m8n8.x4.shared.b16 {%0,%1,%2,%3}, [%4];"
                 : "=r"(r[0]), "=r"(r[1]), "=r"(r[2]), "=r"(r[3]) : "r"(addr));
}
static __device__ __forceinline__ void mma16816(float* c, const uint32_t* a,
                                                uint32_t b0, uint32_t b1) {
    asm volatile("mma.sync.aligned.m16n8k16.row.col.f32.f16.f16.f32 "
                 "{%0,%1,%2,%3}, {%4,%5,%6,%7}, {%8,%9}, {%0,%1,%2,%3};"
                 : "+f"(c[0]), "+f"(c[1]), "+f"(c[2]), "+f"(c[3])
                 : "r"(a[0]), "r"(a[1]), "r"(a[2]), "r"(a[3]), "r"(b0), "r"(b1));
}
static __device__ __forceinline__ void barsync(int id, int cnt) {
    asm volatile("bar.sync %0, %1;" :: "r"(id), "r"(cnt) : "memory");
}
static __device__ __forceinline__ void bararrive(int id, int cnt) {
    asm volatile("bar.arrive %0, %1;" :: "r"(id), "r"(cnt) : "memory");
}
// swizzled byte offset inside a [128row][64k fp16] tile (128B rows, 16B units)
static __device__ __forceinline__ int swz(int row, int unit16) {
    int off = row * 128 + unit16 * 16;
    return off ^ ((off >> 3) & 0x70);
}

// ============================================================================
// prep: split weights fp32 -> (hi, lo) fp16, SW128-swizzled SMEM-image layout.
// ============================================================================
__global__ void prep_kernel(const float* __restrict__ Wl1, const float* __restrict__ Wr1,
                            const float* __restrict__ Wlt1, const float* __restrict__ Wrt1,
                            const float* __restrict__ Wl2, const float* __restrict__ Wr2,
                            const float* __restrict__ Wlt2, const float* __restrict__ Wrt2)
{
    int uid = blockIdx.x * blockDim.x + threadIdx.x;
    if (uid >= 8192 + 4096) return;

    const float *WL, *WR;
    char *hibase, *lobase;
    int v, u, chunk, n, k8;
    if (uid < 8192) {                       // layer 1
        v = uid;
        int y = v >> 12; v &= 4095;
        chunk = v >> 10; v &= 1023;
        n = v >> 3;  k8 = v & 7;
        u = y * 64 + (n >> 1);
        bool zsel = n & 1;
        WL = zsel ? Wl1 : Wlt1;
        WR = zsel ? Wr1 : Wrt1;
        hibase = (char*)&g_W1img[y][0][chunk][0];
        lobase = (char*)&g_W1img[y][1][chunk][0];
    } else {                                // layer 2
        v = uid - 8192;
        chunk = v >> 10; v &= 1023;
        n = v >> 3;  k8 = v & 7;
        u = n >> 1;
        bool zsel = n & 1;
        WL = zsel ? Wl2 : Wlt2;
        WR = zsel ? Wr2 : Wrt2;
        hibase = (char*)&g_W2img[0][chunk][0];
        lobase = (char*)&g_W2img[1][chunk][0];
    }
    int off = n * 128 + k8 * 16;
    off ^= (off >> 3) & 0x70;
    uint32_t hu[4], lu[4];
    #pragma unroll
    for (int j = 0; j < 4; j++) {
        float f0, f1;
        int kg = chunk * 64 + k8 * 8 + 2 * j;
        f0 = (kg < 128) ? WL[u * 128 + kg] : WR[u * 128 + kg - 128];
        kg++;
        f1 = (kg < 128) ? WL[u * 128 + kg] : WR[u * 128 + kg - 128];
        __half h0 = __float2half_rn(f0), h1 = __float2half_rn(f1);
        __half l0 = __float2half_rn(f0 - __half2float(h0));
        __half l1 = __float2half_rn(f1 - __half2float(h1));
        __half2 hp = __halves2half2(h0, h1), lp = __halves2half2(l0, l1);
        hu[j] = *(uint32_t*)&hp; lu[j] = *(uint32_t*)&lp;
    }
    *(uint4*)(hibase + off) = make_uint4(hu[0], hu[1], hu[2], hu[3]);
    *(uint4*)(lobase + off) = make_uint4(lu[0], lu[1], lu[2], lu[3]);
}

// ============================================================================
// mean1: g_means[r] = (r<Nn) ? mean of 5 h1 rows : mean of 2 h2 rows
// ============================================================================
__global__ void mean1_kernel(const float* __restrict__ h1, const float* __restrict__ h2)
{
    int idx = blockIdx.x * blockDim.x + threadIdx.x;
    if (idx >= ROWS1 * 32) return;
    int r = idx >> 5, j = idx & 31;
    float4 s;
    if (r < Nn) {
        const float4* p = (const float4*)(h1 + (size_t)r * 640) + j;
        float4 a = p[0], b = p[32], c = p[64], d = p[96], e = p[128];
        s.x = (a.x + b.x + c.x + d.x + e.x) * 0.2f;
        s.y = (a.y + b.y + c.y + d.y + e.y) * 0.2f;
        s.z = (a.z + b.z + c.z + d.z + e.z) * 0.2f;
        s.w = (a.w + b.w + c.w + d.w + e.w) * 0.2f;
    } else {
        const float4* p = (const float4*)(h2 + (size_t)(r - Nn) * 256) + j;
        float4 a = p[0], b = p[32];
        s.x = (a.x + b.x) * 0.5f;
        s.y = (a.y + b.y) * 0.5f;
        s.z = (a.z + b.z) * 0.5f;
        s.w = (a.w + b.w) * 0.5f;
    }
    *((float4*)(g_means + (size_t)r * 128) + j) = s;
}

// mean for layer 2: g_means[r] = mean of 5 g_outs rows (h1p block)
__global__ void mean2_kernel()
{
    int idx = blockIdx.x * blockDim.x + threadIdx.x;
    if (idx >= Nn * 32) return;
    int r = idx >> 5, j = idx & 31;
    const float4* p = (const float4*)(g_outs + ((size_t)Nn + (size_t)r * 5) * 128) + j;
    float4 a = p[0], b = p[32], c = p[64], d = p[96], e = p[128];
    float4 s;
    s.x = (a.x + b.x + c.x + d.x + e.x) * 0.2f;
    s.y = (a.y + b.y + c.y + d.y + e.y) * 0.2f;
    s.z = (a.z + b.z + c.z + d.z + e.z) * 0.2f;
    s.w = (a.w + b.w + c.w + d.w + e.w) * 0.2f;
    *((float4*)(g_means + (size_t)r * 128) + j) = s;
}

// ============================================================================
// PERSISTENT warp-specialized GEMM, fp16x3 split on mma.sync (HMMA).
// 384 threads: warps 0-7 = MMA consumers (2M x 4N, warp tile 64x32),
//              warps 8-11 = producers (fetch + split-convert A chunks).
// B resident (128 KB). A double-buffered (2 x 32 KB). Named-barrier handoff.
// ============================================================================
#define SM_B    1024
#define SM_A    132096
#define SM_TOT  197632
#define NTHR    384
// named barriers: READY[s] = 1+s, CONSUMED[s] = 3+s
#define BAR_READY(s)    (1 + (s))
#define BAR_CONS(s)     (3 + (s))

extern "C" __global__ void __launch_bounds__(NTHR, 1)
signn_tile_kernel(int mode,
                  const float* __restrict__ h0,
                  const float* __restrict__ h1,
                  float* __restrict__ outp)
{
    extern __shared__ __align__(1024) char smem[];
    const uint32_t sb = smem_u32(smem);
    const int tid = threadIdx.x, lane = tid & 31;
    const int y = blockIdx.x;
    const int nrows = mode ? Nn : ROWS1;
    const int ntiles = (nrows + 127) >> 7;
    const int stride = gridDim.y;

    // ---- stage B once (resident, 128 KB), all 384 threads ----
    {
        const uint4* bsrc = mode ? (const uint4*)&g_W2img[0][0][0]
                                 : (const uint4*)&g_W1img[y][0][0][0];
        uint4* bdst = (uint4*)(smem + SM_B);
        for (int i = tid; i < 8192; i += NTHR) bdst[i] = bsrc[i];
    }
    __syncthreads();

    if (tid < 256) {
        // ===================== CONSUMER: 8 MMA warps =====================
        const int wid = tid >> 5;
        const int wm = wid & 1;          // M warp group: 64 rows
        const int wn = wid >> 1;         // N warp group: 32 cols
        const int lrow = (lane & 7) + ((lane >> 3) & 1) * 8;
        const int lcol = lane >> 4;
        const int qlane = lane >> 2, tlane = lane & 3;

        int s = 0;
        for (int t = blockIdx.y; t < ntiles; t += stride) {
            const int row0 = t * 128;
            float acc[64];
            #pragma unroll
            for (int i = 0; i < 64; i++) acc[i] = 0.0f;

            #pragma unroll
            for (int c = 0; c < 4; c++) {
                barsync(BAR_READY(s), NTHR);          // wait A stage s filled
                const uint32_t aBase = sb + SM_A + s * 32768;
                const uint32_t bBase = sb + SM_B + c * 16384;
                #pragma unroll
                for (int kk = 0; kk < 4; kk++) {
                    uint32_t AH[4][4], AL[4][4], BH[2][4], BL[2][4];
                    #pragma unroll
                    for (int mf = 0; mf < 4; mf++) {
                        int r = wm * 64 + mf * 16 + lrow;
                        int u = kk * 2 + lcol;
                        ldm4(AH[mf], aBase + swz(r, u));
                        ldm4(AL[mf], aBase + 16384 + swz(r, u));
                    }
                    #pragma unroll
                    for (int nb = 0; nb < 2; nb++) {
                        int r = wn * 32 + nb * 16 + lrow;
                        int u = kk * 2 + lcol;
                        ldm4(BH[nb], bBase + swz(r, u));
                        ldm4(BL[nb], bBase + 65536 + swz(r, u));
                    }
                    #pragma unroll
                    for (int mf = 0; mf < 4; mf++)
                        #pragma unroll
                        for (int nb = 0; nb < 2; nb++)
                            #pragma unroll
                            for (int h = 0; h < 2; h++) {
                                float* cc = acc + mf * 16 + (nb * 2 + h) * 4;
                                mma16816(cc, AH[mf], BH[nb][h], BH[nb][2 + h]);
                                mma16816(cc, AH[mf], BL[nb][h], BL[nb][2 + h]);
                                mma16816(cc, AL[mf], BH[nb][h], BH[nb][2 + h]);
                            }
                }
                bararrive(BAR_CONS(s), NTHR);         // A stage s free
                s ^= 1;
            }

            // epilogue (overlaps producers filling next tile)
            #pragma unroll
            for (int mf = 0; mf < 4; mf++) {
                int r0 = row0 + wm * 64 + mf * 16 + qlane;
                #pragma unroll
                for (int nn = 0; nn < 4; nn++) {
                    const float* cc = acc + mf * 16 + nn * 4;
                    int u = wn * 16 + nn * 4 + tlane;
                    #pragma unroll
                    for (int rr = 0; rr < 2; rr++) {
                        int r = r0 + rr * 8;
                        if (r < nrows) {
                            float tt = cc[rr * 2 + 0], zz = cc[rr * 2 + 1];
                            float o = (tt >= 1.0f) ? (1.0f / (1.0f + __expf(-zz))) : 0.0f;
                            if (mode) outp[(size_t)r * 64 + u] = o;
                            else      g_outs[(size_t)r * 128 + y * 64 + u] = o;
                        }
                    }
                }
            }
        }
    } else {
        // ===================== PRODUCER: 4 warps (128 threads) ============
        const int ptid = tid - 256;
        const int k8 = ptid & 7;          // octet within row handled by this thread
        int s = 0;
        long jcount = 0;
        for (int t = blockIdx.y; t < ntiles; t += stride) {
            const int row0 = t * 128;
            #pragma unroll
            for (int c = 0; c < 4; c++) {
                // fetch 8 rows x 1 octet = 16 float4 (issued before stage wait)
                float4 pre[16];
                #pragma unroll
                for (int q = 0; q < 8; q++) {
                    int m = (ptid >> 3) + q * 16;
                    int r = row0 + m;
                    if (r < nrows) {
                        const float* p;
                        if (c < 2) {
                            const float* selfp = mode
                                ? g_outs + (size_t)r * 128
                                : ((r < Nn) ? h0 + (size_t)r * 128
                                            : h1 + (size_t)(r - Nn) * 128);
                            p = selfp + c * 64 + k8 * 8;
                        } else {
                            p = g_means + (size_t)r * 128 + (c - 2) * 64 + k8 * 8;
                        }
                        pre[2 * q]     = *(const float4*)p;
                        pre[2 * q + 1] = *(const float4*)(p + 4);
                    } else {
                        pre[2 * q] = pre[2 * q + 1] = make_float4(0.f, 0.f, 0.f, 0.f);
                    }
                }

                if (jcount >= 2) barsync(BAR_CONS(s), NTHR);   // stage s free?

                char* Ah = smem + SM_A + s * 32768;
                char* Al = Ah + 16384;
                #pragma unroll
                for (int q = 0; q < 8; q++) {
                    int m = (ptid >> 3) + q * 16;
                    float f[8];
                    f[0]=pre[2*q].x; f[1]=pre[2*q].y; f[2]=pre[2*q].z; f[3]=pre[2*q].w;
                    f[4]=pre[2*q+1].x; f[5]=pre[2*q+1].y; f[6]=pre[2*q+1].z; f[7]=pre[2*q+1].w;
                    uint32_t hu[4], lu[4];
                    #pragma unroll
                    for (int j = 0; j < 4; j++) {
                        float x0 = f[2*j], x1 = f[2*j+1];
                        __half hh0 = __float2half_rn(x0), hh1 = __float2half_rn(x1);
                        __half ll0 = __float2half_rn(x0 - __half2float(hh0));
                        __half ll1 = __float2half_rn(x1 - __half2float(hh1));
                        __half2 hp = __halves2half2(hh0, hh1), lp = __halves2half2(ll0, ll1);
                        hu[j] = *(uint32_t*)&hp; lu[j] = *(uint32_t*)&lp;
                    }
                    int off = swz(m, k8);
                    *(uint4*)(Ah + off) = make_uint4(hu[0], hu[1], hu[2], hu[3]);
                    *(uint4*)(Al + off) = make_uint4(lu[0], lu[1], lu[2], lu[3]);
                }
                asm volatile("membar.cta;" ::: "memory");
                bararrive(BAR_READY(s), NTHR);                 // stage s ready
                s ^= 1;
                jcount++;
            }
        }
    }
}

// ============================================================================
extern "C" void kernel_launch(void* const* d_in, const int* in_sizes, int n_in,
                              void* d_out, int out_size)
{
    const float* h0   = (const float*)d_in[0];
    const float* h1   = (const float*)d_in[1];
    const float* h2   = (const float*)d_in[2];
    const float* Wl1  = (const float*)d_in[3];
    const float* Wr1  = (const float*)d_in[4];
    const float* Wlt1 = (const float*)d_in[5];
    const float* Wrt1 = (const float*)d_in[6];
    const float* Wl2  = (const float*)d_in[7];
    const float* Wr2  = (const float*)d_in[8];
    const float* Wlt2 = (const float*)d_in[9];
    const float* Wrt2 = (const float*)d_in[10];
    float* out = (float*)d_out;

    cudaFuncSetAttribute(signn_tile_kernel,
                         cudaFuncAttributeMaxDynamicSharedMemorySize, SM_TOT);

    prep_kernel<<<48, 256>>>(Wl1, Wr1, Wlt1, Wrt1, Wl2, Wr2, Wlt2, Wrt2);
    mean1_kernel<<<(ROWS1 * 32 + 255) / 256, 256>>>(h1, h2);

    dim3 g1(2, 74);                    // 148 persistent CTAs: one y-half each
    signn_tile_kernel<<<g1, NTHR, SM_TOT>>>(0, h0, h1, nullptr);

    mean2_kernel<<<(Nn * 32 + 255) / 256, 256>>>();

    dim3 g2(1, 148);                   // 148 persistent CTAs
    signn_tile_kernel<<<g2, NTHR, SM_TOT>>>(1, nullptr, nullptr, out);
}

// round 8
// speedup vs baseline: 2.1889x; 1.0236x over previous
#include <cuda_runtime.h>
#include <cuda_fp16.h>
#include <cstdint>

#define Nn     100000
#define ROWS1  600000

// ---------------- device scratch (static globals: allocation-free) ----------
__device__ __align__(1024) __half g_W1img[2][2][4][8192];  // [y][comp][chunk][128n x 64k] swizzled
__device__ __align__(1024) __half g_W2img[2][4][8192];     // [comp][chunk][...]
__device__ __align__(128)  float  g_outs[(size_t)ROWS1 * 128];
__device__ __align__(128)  float  g_means[(size_t)ROWS1 * 128];

// ---------------- helpers ---------------------------------------------------
static __device__ __forceinline__ uint32_t smem_u32(const void* p) {
    uint32_t a;
    asm("{ .reg .u64 t; cvta.to.shared.u64 t, %1; cvt.u32.u64 %0, t; }" : "=r"(a) : "l"(p));
    return a;
}
static __device__ __forceinline__ void ldm4(uint32_t* r, uint32_t addr) {
    asm volatile("ldmatrix.sync.aligned.m8n8.x4.shared.b16 {%0,%1,%2,%3}, [%4];"
                 : "=r"(r[0]), "=r"(r[1]), "=r"(r[2]), "=r"(r[3]) : "r"(addr));
}
static __device__ __forceinline__ void mma16816(float* c, const uint32_t* a,
                                                uint32_t b0, uint32_t b1) {
    asm volatile("mma.sync.aligned.m16n8k16.row.col.f32.f16.f16.f32 "
                 "{%0,%1,%2,%3}, {%4,%5,%6,%7}, {%8,%9}, {%0,%1,%2,%3};"
                 : "+f"(c[0]), "+f"(c[1]), "+f"(c[2]), "+f"(c[3])
                 : "r"(a[0]), "r"(a[1]), "r"(a[2]), "r"(a[3]), "r"(b0), "r"(b1));
}
// f16-accumulate variant: D/C are 2 packed f16x2 regs
static __device__ __forceinline__ void mma16816h(uint32_t* c, const uint32_t* a,
                                                 uint32_t b0, uint32_t b1) {
    asm volatile("mma.sync.aligned.m16n8k16.row.col.f16.f16.f16.f16 "
                 "{%0,%1}, {%2,%3,%4,%5}, {%6,%7}, {%0,%1};"
                 : "+r"(c[0]), "+r"(c[1])
                 : "r"(a[0]), "r"(a[1]), "r"(a[2]), "r"(a[3]), "r"(b0), "r"(b1));
}
static __device__ __forceinline__ void barsync(int id, int cnt) {
    asm volatile("bar.sync %0, %1;" :: "r"(id), "r"(cnt) : "memory");
}
static __device__ __forceinline__ void bararrive(int id, int cnt) {
    asm volatile("bar.arrive %0, %1;" :: "r"(id), "r"(cnt) : "memory");
}
// swizzled byte offset inside a [128row][64k fp16] tile (128B rows, 16B units)
static __device__ __forceinline__ int swz(int row, int unit16) {
    int off = row * 128 + unit16 * 16;
    return off ^ ((off >> 3) & 0x70);
}

// ============================================================================
// prep: split weights fp32 -> (hi, lo) fp16, SW128-swizzled SMEM-image layout.
// ============================================================================
__global__ void prep_kernel(const float* __restrict__ Wl1, const float* __restrict__ Wr1,
                            const float* __restrict__ Wlt1, const float* __restrict__ Wrt1,
                            const float* __restrict__ Wl2, const float* __restrict__ Wr2,
                            const float* __restrict__ Wlt2, const float* __restrict__ Wrt2)
{
    int uid = blockIdx.x * blockDim.x + threadIdx.x;
    if (uid >= 8192 + 4096) return;

    const float *WL, *WR;
    char *hibase, *lobase;
    int v, u, chunk, n, k8;
    if (uid < 8192) {                       // layer 1
        v = uid;
        int y = v >> 12; v &= 4095;
        chunk = v >> 10; v &= 1023;
        n = v >> 3;  k8 = v & 7;
        u = y * 64 + (n >> 1);
        bool zsel = n & 1;
        WL = zsel ? Wl1 : Wlt1;
        WR = zsel ? Wr1 : Wrt1;
        hibase = (char*)&g_W1img[y][0][chunk][0];
        lobase = (char*)&g_W1img[y][1][chunk][0];
    } else {                                // layer 2
        v = uid - 8192;
        chunk = v >> 10; v &= 1023;
        n = v >> 3;  k8 = v & 7;
        u = n >> 1;
        bool zsel = n & 1;
        WL = zsel ? Wl2 : Wlt2;
        WR = zsel ? Wr2 : Wrt2;
        hibase = (char*)&g_W2img[0][chunk][0];
        lobase = (char*)&g_W2img[1][chunk][0];
    }
    int off = n * 128 + k8 * 16;
    off ^= (off >> 3) & 0x70;
    uint32_t hu[4], lu[4];
    #pragma unroll
    for (int j = 0; j < 4; j++) {
        float f0, f1;
        int kg = chunk * 64 + k8 * 8 + 2 * j;
        f0 = (kg < 128) ? WL[u * 128 + kg] : WR[u * 128 + kg - 128];
        kg++;
        f1 = (kg < 128) ? WL[u * 128 + kg] : WR[u * 128 + kg - 128];
        __half h0 = __float2half_rn(f0), h1 = __float2half_rn(f1);
        __half l0 = __float2half_rn(f0 - __half2float(h0));
        __half l1 = __float2half_rn(f1 - __half2float(h1));
        __half2 hp = __halves2half2(h0, h1), lp = __halves2half2(l0, l1);
        hu[j] = *(uint32_t*)&hp; lu[j] = *(uint32_t*)&lp;
    }
    *(uint4*)(hibase + off) = make_uint4(hu[0], hu[1], hu[2], hu[3]);
    *(uint4*)(lobase + off) = make_uint4(lu[0], lu[1], lu[2], lu[3]);
}

// ============================================================================
// mean1: g_means[r] = (r<Nn) ? mean of 5 h1 rows : mean of 2 h2 rows
// ============================================================================
__global__ void mean1_kernel(const float* __restrict__ h1, const float* __restrict__ h2)
{
    int idx = blockIdx.x * blockDim.x + threadIdx.x;
    if (idx >= ROWS1 * 32) return;
    int r = idx >> 5, j = idx & 31;
    float4 s;
    if (r < Nn) {
        const float4* p = (const float4*)(h1 + (size_t)r * 640) + j;
        float4 a = p[0], b = p[32], c = p[64], d = p[96], e = p[128];
        s.x = (a.x + b.x + c.x + d.x + e.x) * 0.2f;
        s.y = (a.y + b.y + c.y + d.y + e.y) * 0.2f;
        s.z = (a.z + b.z + c.z + d.z + e.z) * 0.2f;
        s.w = (a.w + b.w + c.w + d.w + e.w) * 0.2f;
    } else {
        const float4* p = (const float4*)(h2 + (size_t)(r - Nn) * 256) + j;
        float4 a = p[0], b = p[32];
        s.x = (a.x + b.x) * 0.5f;
        s.y = (a.y + b.y) * 0.5f;
        s.z = (a.z + b.z) * 0.5f;
        s.w = (a.w + b.w) * 0.5f;
    }
    *((float4*)(g_means + (size_t)r * 128) + j) = s;
}

// mean for layer 2: g_means[r] = mean of 5 g_outs rows (h1p block)
__global__ void mean2_kernel()
{
    int idx = blockIdx.x * blockDim.x + threadIdx.x;
    if (idx >= Nn * 32) return;
    int r = idx >> 5, j = idx & 31;
    const float4* p = (const float4*)(g_outs + ((size_t)Nn + (size_t)r * 5) * 128) + j;
    float4 a = p[0], b = p[32], c = p[64], d = p[96], e = p[128];
    float4 s;
    s.x = (a.x + b.x + c.x + d.x + e.x) * 0.2f;
    s.y = (a.y + b.y + c.y + d.y + e.y) * 0.2f;
    s.z = (a.z + b.z + c.z + d.z + e.z) * 0.2f;
    s.w = (a.w + b.w + c.w + d.w + e.w) * 0.2f;
    *((float4*)(g_means + (size_t)r * 128) + j) = s;
}

// ============================================================================
// PERSISTENT warp-specialized GEMM, fp16x3 split on mma.sync (HMMA).
// Pass 1 (Ah*Bh) -> f32 accum; passes 2,3 (Ah*Bl, Al*Bh) -> shared f16 accum.
// 384 threads: warps 0-7 MMA consumers (2M x 4N), warps 8-11 producers.
// B resident (128 KB). A double-buffered (2 x 32 KB). Named-barrier handoff.
// ============================================================================
#define SM_B    1024
#define SM_A    132096
#define SM_TOT  197632
#define NTHR    384
#define BAR_READY(s)    (1 + (s))
#define BAR_CONS(s)     (3 + (s))

extern "C" __global__ void __launch_bounds__(NTHR, 1)
signn_tile_kernel(int mode,
                  const float* __restrict__ h0,
                  const float* __restrict__ h1,
                  float* __restrict__ outp)
{
    extern __shared__ __align__(1024) char smem[];
    const uint32_t sb = smem_u32(smem);
    const int tid = threadIdx.x, lane = tid & 31;
    const int y = blockIdx.x;
    const int nrows = mode ? Nn : ROWS1;
    const int ntiles = (nrows + 127) >> 7;
    const int stride = gridDim.y;

    // ---- stage B once (resident, 128 KB), all 384 threads ----
    {
        const uint4* bsrc = mode ? (const uint4*)&g_W2img[0][0][0]
                                 : (const uint4*)&g_W1img[y][0][0][0];
        uint4* bdst = (uint4*)(smem + SM_B);
        for (int i = tid; i < 8192; i += NTHR) bdst[i] = bsrc[i];
    }
    __syncthreads();

    if (tid < 256) {
        // ===================== CONSUMER: 8 MMA warps =====================
        const int wid = tid >> 5;
        const int wm = wid & 1;          // M warp group: 64 rows
        const int wn = wid >> 1;         // N warp group: 32 cols
        const int lrow = (lane & 7) + ((lane >> 3) & 1) * 8;
        const int lcol = lane >> 4;
        const int qlane = lane >> 2, tlane = lane & 3;

        int s = 0;
        for (int t = blockIdx.y; t < ntiles; t += stride) {
            const int row0 = t * 128;
            float acc[64];
            uint32_t accl[32];               // f16x2 accum for low passes
            #pragma unroll
            for (int i = 0; i < 64; i++) acc[i] = 0.0f;
            #pragma unroll
            for (int i = 0; i < 32; i++) accl[i] = 0u;

            #pragma unroll
            for (int c = 0; c < 4; c++) {
                barsync(BAR_READY(s), NTHR);          // wait A stage s filled
                const uint32_t aBase = sb + SM_A + s * 32768;
                const uint32_t bBase = sb + SM_B + c * 16384;
                #pragma unroll
                for (int kk = 0; kk < 4; kk++) {
                    uint32_t AH[4][4], AL[4][4], BH[2][4], BL[2][4];
                    #pragma unroll
                    for (int mf = 0; mf < 4; mf++) {
                        int r = wm * 64 + mf * 16 + lrow;
                        int u = kk * 2 + lcol;
                        ldm4(AH[mf], aBase + swz(r, u));
                        ldm4(AL[mf], aBase + 16384 + swz(r, u));
                    }
                    #pragma unroll
                    for (int nb = 0; nb < 2; nb++) {
                        int r = wn * 32 + nb * 16 + lrow;
                        int u = kk * 2 + lcol;
                        ldm4(BH[nb], bBase + swz(r, u));
                    }
                    // pass 1 (f32 acc) + pass 3 (f16 acc) use BH
                    #pragma unroll
                    for (int mf = 0; mf < 4; mf++)
                        #pragma unroll
                        for (int nb = 0; nb < 2; nb++)
                            #pragma unroll
                            for (int h = 0; h < 2; h++) {
                                mma16816(acc + mf * 16 + (nb * 2 + h) * 4,
                                         AH[mf], BH[nb][h], BH[nb][2 + h]);
                                mma16816h(accl + mf * 8 + (nb * 2 + h) * 2,
                                          AL[mf], BH[nb][h], BH[nb][2 + h]);
                            }
                    // pass 2 (f16 acc) uses BL
                    #pragma unroll
                    for (int nb = 0; nb < 2; nb++) {
                        int r = wn * 32 + nb * 16 + lrow;
                        int u = kk * 2 + lcol;
                        ldm4(BL[nb], bBase + 65536 + swz(r, u));
                    }
                    #pragma unroll
                    for (int mf = 0; mf < 4; mf++)
                        #pragma unroll
                        for (int nb = 0; nb < 2; nb++)
                            #pragma unroll
                            for (int h = 0; h < 2; h++)
                                mma16816h(accl + mf * 8 + (nb * 2 + h) * 2,
                                          AH[mf], BL[nb][h], BL[nb][2 + h]);
                }
                bararrive(BAR_CONS(s), NTHR);         // A stage s free
                s ^= 1;
            }

            // epilogue: merge f32 + f16 accums, apply sigmoid*spike
            #pragma unroll
            for (int mf = 0; mf < 4; mf++) {
                int r0 = row0 + wm * 64 + mf * 16 + qlane;
                #pragma unroll
                for (int nn = 0; nn < 4; nn++) {
                    const float* cc = acc + mf * 16 + nn * 4;
                    const uint32_t* cl = accl + mf * 8 + nn * 2;
                    int u = wn * 16 + nn * 4 + tlane;
                    #pragma unroll
                    for (int rr = 0; rr < 2; rr++) {
                        int r = r0 + rr * 8;
                        if (r < nrows) {
                            float2 lo = __half22float2(*(const __half2*)&cl[rr]);
                            float tt = cc[rr * 2 + 0] + lo.x;
                            float zz = cc[rr * 2 + 1] + lo.y;
                            float o = (tt >= 1.0f) ? (1.0f / (1.0f + __expf(-zz))) : 0.0f;
                            if (mode) outp[(size_t)r * 64 + u] = o;
                            else      g_outs[(size_t)r * 128 + y * 64 + u] = o;
                        }
                    }
                }
            }
        }
    } else {
        // ===================== PRODUCER: 4 warps (128 threads) ============
        const int ptid = tid - 256;
        const int k8 = ptid & 7;
        int s = 0;
        long jcount = 0;
        for (int t = blockIdx.y; t < ntiles; t += stride) {
            const int row0 = t * 128;
            #pragma unroll
            for (int c = 0; c < 4; c++) {
                float4 pre[16];
                #pragma unroll
                for (int q = 0; q < 8; q++) {
                    int m = (ptid >> 3) + q * 16;
                    int r = row0 + m;
                    if (r < nrows) {
                        const float* p;
                        if (c < 2) {
                            const float* selfp = mode
                                ? g_outs + (size_t)r * 128
                                : ((r < Nn) ? h0 + (size_t)r * 128
                                            : h1 + (size_t)(r - Nn) * 128);
                            p = selfp + c * 64 + k8 * 8;
                        } else {
                            p = g_means + (size_t)r * 128 + (c - 2) * 64 + k8 * 8;
                        }
                        pre[2 * q]     = *(const float4*)p;
                        pre[2 * q + 1] = *(const float4*)(p + 4);
                    } else {
                        pre[2 * q] = pre[2 * q + 1] = make_float4(0.f, 0.f, 0.f, 0.f);
                    }
                }

                if (jcount >= 2) barsync(BAR_CONS(s), NTHR);

                char* Ah = smem + SM_A + s * 32768;
                char* Al = Ah + 16384;
                #pragma unroll
                for (int q = 0; q < 8; q++) {
                    int m = (ptid >> 3) + q * 16;
                    float f[8];
                    f[0]=pre[2*q].x; f[1]=pre[2*q].y; f[2]=pre[2*q].z; f[3]=pre[2*q].w;
                    f[4]=pre[2*q+1].x; f[5]=pre[2*q+1].y; f[6]=pre[2*q+1].z; f[7]=pre[2*q+1].w;
                    uint32_t hu[4], lu[4];
                    #pragma unroll
                    for (int j = 0; j < 4; j++) {
                        float x0 = f[2*j], x1 = f[2*j+1];
                        __half hh0 = __float2half_rn(x0), hh1 = __float2half_rn(x1);
                        __half ll0 = __float2half_rn(x0 - __half2float(hh0));
                        __half ll1 = __float2half_rn(x1 - __half2float(hh1));
                        __half2 hp = __halves2half2(hh0, hh1), lp = __halves2half2(ll0, ll1);
                        hu[j] = *(uint32_t*)&hp; lu[j] = *(uint32_t*)&lp;
                    }
                    int off = swz(m, k8);
                    *(uint4*)(Ah + off) = make_uint4(hu[0], hu[1], hu[2], hu[3]);
                    *(uint4*)(Al + off) = make_uint4(lu[0], lu[1], lu[2], lu[3]);
                }
                asm volatile("membar.cta;" ::: "memory");
                bararrive(BAR_READY(s), NTHR);
                s ^= 1;
                jcount++;
            }
        }
    }
}

// ============================================================================
extern "C" void kernel_launch(void* const* d_in, const int* in_sizes, int n_in,
                              void* d_out, int out_size)
{
    const float* h0   = (const float*)d_in[0];
    const float* h1   = (const float*)d_in[1];
    const float* h2   = (const float*)d_in[2];
    const float* Wl1  = (const float*)d_in[3];
    const float* Wr1  = (const float*)d_in[4];
    const float* Wlt1 = (const float*)d_in[5];
    const float* Wrt1 = (const float*)d_in[6];
    const float* Wl2  = (const float*)d_in[7];
    const float* Wr2  = (const float*)d_in[8];
    const float* Wlt2 = (const float*)d_in[9];
    const float* Wrt2 = (const float*)d_in[10];
    float* out = (float*)d_out;

    cudaFuncSetAttribute(signn_tile_kernel,
                         cudaFuncAttributeMaxDynamicSharedMemorySize, SM_TOT);

    prep_kernel<<<48, 256>>>(Wl1, Wr1, Wlt1, Wrt1, Wl2, Wr2, Wlt2, Wrt2);
    mean1_kernel<<<(ROWS1 * 32 + 255) / 256, 256>>>(h1, h2);

    dim3 g1(2, 74);                    // 148 persistent CTAs
    signn_tile_kernel<<<g1, NTHR, SM_TOT>>>(0, h0, h1, nullptr);

    mean2_kernel<<<(Nn * 32 + 255) / 256, 256>>>();

    dim3 g2(1, 148);                   // 148 persistent CTAs
    signn_tile_kernel<<<g2, NTHR, SM_TOT>>>(1, nullptr, nullptr, out);
}